// round 13
// baseline (speedup 1.0000x reference)
#include <cuda_runtime.h>

typedef unsigned long long u64;

#define H_      51
#define TSTEPS  512
#define BTOT    1024
#define NB      8
#define NBLK    (BTOT / NB)        // 128
#define NTHR    512
#define GP      224                // padded gate slots, permuted s = 4u+q
#define HROW    108                // per-batch h row: h1[0:51],pad,h2[52:103],pad
#define HC      27                 // ulonglong2 chunks per h row
#define PRB     228                // partial per-batch stride (bank-clean, 16B-align)
#define LVLSZ   (NB * PRB)         // 1824 floats per partial level

// ---- shared memory layout (float offsets) ----
#define OFF_W1   0                          // [13][224] 16B chunks (staging)
#define OFF_W2   (OFF_W1 + 13*GP*4)         // [26][224]
#define OFF_XS   (OFF_W2 + 26*GP*4)         // [512][8]
#define OFF_HS   (OFF_XS + TSTEPS*8)        // [8][108]
#define OFF_C1   (OFF_HS + NB*HROW)         // [8][52]
#define OFF_C2   (OFF_C1 + NB*52)           // [8][52]
#define OFF_PB1  (OFF_C2 + NB*52)           // 2 levels x [8][228]
#define OFF_PB2  (OFF_PB1 + 2*LVLSZ)        // 4 levels x [8][228]
#define OFF_B1   (OFF_PB2 + 4*LVLSZ)        // 224, slot order (u,q)
#define OFF_B2   (OFF_B1 + GP)              // 224
#define OFF_WI1  (OFF_B2 + GP)              // 224
#define OFF_WL   (OFF_WI1 + GP)             // 56
#define OFF_BL   (OFF_WL + 56)              // 4
#define SMEM_FLOATS (OFF_BL + 4)
#define SMEM_BYTES  (SMEM_FLOATS * 4)       // ~205 KB

__device__ __forceinline__ void ffma2(u64 &d, u64 a, u64 b) {
    asm("fma.rn.f32x2 %0, %1, %2, %0;" : "+l"(d) : "l"(a), "l"(b));
}
__device__ __forceinline__ float2 unpk(u64 v) {
    float2 r;
    asm("mov.b64 {%0, %1}, %2;" : "=f"(r.x), "=f"(r.y) : "l"(v));
    return r;
}
__device__ __forceinline__ float sigf(float x) {
    return __fdividef(1.0f, 1.0f + __expf(-x));
}
__device__ __forceinline__ float tanhfast(float x) {
    return __fdividef(2.0f, 1.0f + __expf(-2.0f * x)) - 1.0f;
}

// ---- role/segment tables: 16 warps, <=3 segments each ----
// seg = (Layer, JPair, K0, CNT, Level, AddX). JPair 0..2 = j{2p,2p+1} (NJ2),
// JPair 3 = j6 (NJ1). Weights of a segment live in REGISTERS for all 512 steps.
constexpr int SL[16][3] = {
 {1,2,2},{1,1,2},{1,2,2},{1,1,2},{1,2,2},{1,2,2},{2,2,2},{2,2,2},
 {2,2,2},{2,2,2},{2,2,2},{2,2,2},{2,2,2},{2,2,2},{2,2,2},{2,2,2}};
constexpr int SJ[16][3] = {
 {0,0,0},{0,3,0},{1,0,0},{1,3,3},{2,0,0},{2,3,0},{3,0,0},{0,0,0},
 {0,0,0},{0,1,0},{1,0,0},{1,0,0},{1,2,0},{2,0,0},{2,0,0},{2,0,0}};
constexpr int SK[16][3] = {
 {0,0,0},{9,0,0},{0,0,0},{9,9,0},{0,0,0},{9,5,0},{14,0,0},{3,0,0},
 {12,0,0},{20,0,0},{3,0,0},{12,0,0},{20,0,0},{3,0,0},{12,0,0},{20,0,0}};
constexpr int SC[16][3] = {
 {9,0,0},{4,9,0},{9,0,0},{4,4,5},{9,0,0},{4,9,0},{12,3,0},{9,0,0},
 {8,0,0},{6,3,0},{9,0,0},{8,0,0},{6,3,0},{9,0,0},{8,0,0},{6,0,0}};
constexpr int SV[16][3] = {
 {0,0,0},{1,0,0},{0,0,0},{1,1,0},{0,0,0},{1,1,0},{2,0,0},{1,0,0},
 {2,0,0},{3,0,0},{1,0,0},{2,0,0},{3,0,0},{1,0,0},{2,0,0},{3,0,0}};
constexpr int SX[16][3] = {
 {1,0,0},{0,1,0},{1,0,0},{0,0,0},{1,0,0},{0,0,0},{0,0,0},{0,0,0},
 {0,0,0},{0,0,0},{0,0,0},{0,0,0},{0,0,0},{0,0,0},{0,0,0},{0,0,0}};

template<int L, int JP, int K0, int CNT, int LVL, int X>
struct Seg {
    static constexpr int  NJ   = (JP == 3) ? 1 : 2;
    static constexpr int  CS   = (CNT > 0) ? CNT : 1;
    static constexpr bool ISL1 = (L == 1) && (CNT > 0);
    static constexpr bool ISL2 = (L == 2) && (CNT > 0);
    ulonglong2 w[CS][NJ];
    float wi[NJ];

    __device__ __forceinline__ void load(const float* sm, int lane) {
        if constexpr (CNT > 0) {
            const ulonglong2* wp =
                (const ulonglong2*)(sm + (L == 1 ? OFF_W1 : OFF_W2));
#pragma unroll
            for (int i = 0; i < CNT; i++)
#pragma unroll
                for (int j = 0; j < NJ; j++)
                    w[i][j] = wp[(K0 + i) * GP + lane
                                 + 32 * ((JP == 3) ? 6 : (2 * JP + j))];
            if constexpr (X) {
#pragma unroll
                for (int j = 0; j < NJ; j++)
                    wi[j] = sm[OFF_WI1 + lane
                               + 32 * ((JP == 3) ? 6 : (2 * JP + j))];
            }
        }
    }

    // gate GEMV over this segment for all 8 batches (2 passes of 4),
    // k-paired f32x2 FMA; weights from registers, h broadcast from smem.
    __device__ __forceinline__ void exec(float* sm, int lane,
                                         const float* xrow) const {
        if constexpr (CNT > 0) {
            float* pbl = sm + (L == 1 ? OFF_PB1 : OFF_PB2) + LVL * LVLSZ
                       + lane + 32 * ((JP == 3) ? 6 : (2 * JP));
            const ulonglong2* hp = (const ulonglong2*)(sm + OFF_HS) + K0;
#pragma unroll
            for (int half = 0; half < 2; half++) {
                u64 acc[NJ][4];
#pragma unroll
                for (int j = 0; j < NJ; j++)
#pragma unroll
                    for (int b = 0; b < 4; b++) acc[j][b] = 0ull;
#pragma unroll
                for (int i = 0; i < CNT; i++) {
                    ulonglong2 h[4];
#pragma unroll
                    for (int b = 0; b < 4; b++)
                        h[b] = hp[(half * 4 + b) * HC + i];
#pragma unroll
                    for (int j = 0; j < NJ; j++)
#pragma unroll
                        for (int b = 0; b < 4; b++) {
                            ffma2(acc[j][b], w[i][j].x, h[b].x);
                            ffma2(acc[j][b], w[i][j].y, h[b].y);
                        }
                }
#pragma unroll
                for (int b = 0; b < 4; b++) {
                    int gb = half * 4 + b;
#pragma unroll
                    for (int j = 0; j < NJ; j++) {
                        float2 p = unpk(acc[j][b]);
                        float gv = p.x + p.y;
                        if constexpr (X) gv = fmaf(xrow[gb], wi[j], gv);
                        pbl[gb * PRB + 32 * j] = gv;
                    }
                }
            }
        }
    }
};

// pointwise update, (u,q)-packed float4 reads. One copy (noinline) to
// keep I$ small across the 16 role instantiations.
__device__ __noinline__ void cell_update(int b, int u, bool act,
                                         bool doU2, bool doU1)
{
    extern __shared__ float sm[];
    if (!act) return;
    if (doU2) {
        const float* pb = sm + OFF_PB2 + b * PRB + 4 * u;
        float4 g = *(const float4*)(sm + OFF_B2 + 4 * u);
#pragma unroll
        for (int l = 0; l < 4; l++) {
            float4 p = *(const float4*)(pb + l * LVLSZ);
            g.x += p.x; g.y += p.y; g.z += p.z; g.w += p.w;
        }
        float c  = sm[OFF_C2 + b * 52 + u];
        float cn = sigf(g.y) * c + sigf(g.x) * tanhfast(g.z);
        float hn = sigf(g.w) * tanhfast(cn);
        sm[OFF_C2 + b * 52 + u] = cn;
        sm[OFF_HS + b * HROW + 52 + u] = hn;
    }
    if (doU1) {
        const float* pb = sm + OFF_PB1 + b * PRB + 4 * u;
        float4 g = *(const float4*)(sm + OFF_B1 + 4 * u);
#pragma unroll
        for (int l = 0; l < 2; l++) {
            float4 p = *(const float4*)(pb + l * LVLSZ);
            g.x += p.x; g.y += p.y; g.z += p.z; g.w += p.w;
        }
        float c  = sm[OFF_C1 + b * 52 + u];
        float cn = sigf(g.y) * c + sigf(g.x) * tanhfast(g.z);
        float hn = sigf(g.w) * tanhfast(cn);
        sm[OFF_C1 + b * 52 + u] = cn;
        sm[OFF_HS + b * HROW + u] = hn;
    }
}

__device__ __forceinline__ void out_phase(const float* sm, int lane, int bid,
                                          int tcol, float* __restrict__ out)
{
    int ob = lane & 7, part = lane >> 3;            // 4 parts x 13 k
    float a = 0.0f;
#pragma unroll
    for (int kk = 0; kk < 13; kk++) {
        int k = part * 13 + kk;                     // k=51 -> zero pad
        a = fmaf(sm[OFF_HS + ob * HROW + 52 + k], sm[OFF_WL + k], a);
    }
    a += __shfl_xor_sync(0xffffffffu, a, 8);
    a += __shfl_xor_sync(0xffffffffu, a, 16);
    if (lane < 8)
        out[(bid * NB + ob) * TSTEPS + tcol] = a + sm[OFF_BL];
}

template<int R>
__device__ __forceinline__ void role_loop(float* sm, int lane, int tid,
                                          int bid, float* __restrict__ out)
{
    using S0 = Seg<SL[R][0], SJ[R][0], SK[R][0], SC[R][0], SV[R][0], SX[R][0]>;
    using S1 = Seg<SL[R][1], SJ[R][1], SK[R][1], SC[R][1], SV[R][1], SX[R][1]>;
    using S2 = Seg<SL[R][2], SJ[R][2], SK[R][2], SC[R][2], SV[R][2], SX[R][2]>;
    S0 s0; S1 s1; S2 s2;
    s0.load(sm, lane); s1.load(sm, lane); s2.load(sm, lane);

    const int  ub   = tid & 7;
    const int  uu   = tid >> 3;
    const bool uact = tid < NB * H_;

    // ---- prologue: G1(0), U1(0) ----
    {
        const float* xr = sm + OFF_XS;
        if constexpr (S0::ISL1) s0.exec(sm, lane, xr);
        if constexpr (S1::ISL1) s1.exec(sm, lane, xr);
        if constexpr (S2::ISL1) s2.exec(sm, lane, xr);
    }
    __syncthreads();
    cell_update(ub, uu, uact, false, true);
    __syncthreads();

    // ---- pipelined recurrence ----
    for (int t = 0; t < TSTEPS; t++) {
        // phase A: G2(t) + G1(t+1) + out(t-1)
        if constexpr (S0::ISL2) s0.exec(sm, lane, nullptr);
        if constexpr (S1::ISL2) s1.exec(sm, lane, nullptr);
        if constexpr (S2::ISL2) s2.exec(sm, lane, nullptr);
        if (t + 1 < TSTEPS) {
            const float* xr = sm + OFF_XS + (t + 1) * 8;
            if constexpr (S0::ISL1) s0.exec(sm, lane, xr);
            if constexpr (S1::ISL1) s1.exec(sm, lane, xr);
            if constexpr (S2::ISL1) s2.exec(sm, lane, xr);
        }
        if (R == 15 && t > 0) out_phase(sm, lane, bid, t - 1, out);
        __syncthreads();

        // phase B: U2(t) + U1(t+1)
        cell_update(ub, uu, uact, true, t + 1 < TSTEPS);
        __syncthreads();
    }

    if (R == 15) out_phase(sm, lane, bid, TSTEPS - 1, out);
}

__global__ void __launch_bounds__(NTHR, 1)
lstm_kernel(const float* __restrict__ input,
            const float* __restrict__ Wih1, const float* __restrict__ Whh1,
            const float* __restrict__ bih1, const float* __restrict__ bhh1,
            const float* __restrict__ Wih2, const float* __restrict__ Whh2,
            const float* __restrict__ bih2, const float* __restrict__ bhh2,
            const float* __restrict__ Wlin, const float* __restrict__ blin,
            float* __restrict__ out)
{
    extern __shared__ float sm[];
    const int tid  = threadIdx.x;
    const int bid  = blockIdx.x;
    const int lane = tid & 31;
    const int wid  = tid >> 5;            // 0..15

    // ---- staging (slot s = 4u+q; original gate row og = q*51+u) ----
    for (int i = tid; i < NB * HROW; i += NTHR) sm[OFF_HS + i] = 0.0f;
    for (int i = tid; i < NB * 52 * 2; i += NTHR) sm[OFF_C1 + i] = 0.0f;
    for (int i = tid; i < 6 * LVLSZ; i += NTHR) sm[OFF_PB1 + i] = 0.0f;
    for (int i = tid; i < TSTEPS * 8; i += NTHR) {
        int t = i >> 3, bb = i & 7;
        sm[OFF_XS + i] = input[t * BTOT + bid * NB + bb];
    }
    for (int i = tid; i < 13 * GP * 4; i += NTHR) {
        int c = i & 3, s = (i >> 2) % GP, kq = i / (GP * 4);
        int u = s >> 2, q = s & 3, k = 4 * kq + c;
        float v = 0.0f;
        if (u < H_ && k < H_) v = Whh1[(q * H_ + u) * H_ + k];
        sm[OFF_W1 + i] = v;
    }
    for (int i = tid; i < 26 * GP * 4; i += NTHR) {
        int c = i & 3, s = (i >> 2) % GP, kq = i / (GP * 4);
        int u = s >> 2, q = s & 3, k = 4 * kq + c;
        float v = 0.0f;
        if (u < H_) {
            if (k < H_)                  v = Wih2[(q * H_ + u) * H_ + k];
            else if (k >= 52 && k < 103) v = Whh2[(q * H_ + u) * H_ + (k - 52)];
        }
        sm[OFF_W2 + i] = v;
    }
    for (int i = tid; i < GP; i += NTHR) {
        int u = i >> 2, q = i & 3;
        float b1 = 0.0f, b2 = 0.0f, w1 = 0.0f;
        if (u < H_) {
            int og = q * H_ + u;
            b1 = bih1[og] + bhh1[og];
            b2 = bih2[og] + bhh2[og];
            w1 = Wih1[og];
        }
        sm[OFF_B1  + i] = b1;
        sm[OFF_B2  + i] = b2;
        sm[OFF_WI1 + i] = w1;
    }
    if (tid < 56) sm[OFF_WL + tid] = (tid < H_) ? Wlin[tid] : 0.0f;
    if (tid == 0) sm[OFF_BL] = blin[0];
    __syncthreads();

    switch (wid) {
        case 0:  role_loop<0>(sm, lane, tid, bid, out);  break;
        case 1:  role_loop<1>(sm, lane, tid, bid, out);  break;
        case 2:  role_loop<2>(sm, lane, tid, bid, out);  break;
        case 3:  role_loop<3>(sm, lane, tid, bid, out);  break;
        case 4:  role_loop<4>(sm, lane, tid, bid, out);  break;
        case 5:  role_loop<5>(sm, lane, tid, bid, out);  break;
        case 6:  role_loop<6>(sm, lane, tid, bid, out);  break;
        case 7:  role_loop<7>(sm, lane, tid, bid, out);  break;
        case 8:  role_loop<8>(sm, lane, tid, bid, out);  break;
        case 9:  role_loop<9>(sm, lane, tid, bid, out);  break;
        case 10: role_loop<10>(sm, lane, tid, bid, out); break;
        case 11: role_loop<11>(sm, lane, tid, bid, out); break;
        case 12: role_loop<12>(sm, lane, tid, bid, out); break;
        case 13: role_loop<13>(sm, lane, tid, bid, out); break;
        case 14: role_loop<14>(sm, lane, tid, bid, out); break;
        default: role_loop<15>(sm, lane, tid, bid, out); break;
    }
}

extern "C" void kernel_launch(void* const* d_in, const int* in_sizes, int n_in,
                              void* d_out, int out_size)
{
    const float* input = (const float*)d_in[0];
    const float* Wih1  = (const float*)d_in[1];
    const float* Whh1  = (const float*)d_in[2];
    const float* bih1  = (const float*)d_in[3];
    const float* bhh1  = (const float*)d_in[4];
    const float* Wih2  = (const float*)d_in[5];
    const float* Whh2  = (const float*)d_in[6];
    const float* bih2  = (const float*)d_in[7];
    const float* bhh2  = (const float*)d_in[8];
    const float* Wlin  = (const float*)d_in[9];
    const float* blin  = (const float*)d_in[10];
    float* out = (float*)d_out;

    static bool attr_set = false;
    if (!attr_set) {
        cudaFuncSetAttribute(lstm_kernel,
                             cudaFuncAttributeMaxDynamicSharedMemorySize,
                             SMEM_BYTES);
        attr_set = true;
    }
    lstm_kernel<<<NBLK, NTHR, SMEM_BYTES>>>(input, Wih1, Whh1, bih1, bhh1,
                                            Wih2, Whh2, bih2, bhh2,
                                            Wlin, blin, out);
}

// round 15
// speedup vs baseline: 1.7658x; 1.7658x over previous
#include <cuda_runtime.h>

typedef unsigned long long u64;

#define H_      51
#define TSTEPS  512
#define BTOT    1024
#define NB      8
#define NBLK    (BTOT / NB)        // 128
#define NTHR    384
#define GP      224                // padded gate slots, permuted s = 4u+q
#define HROW    108                // per-batch h row: h1[0:51],pad,h2[52:103],pad
#define HC      27                 // ulonglong2 chunks per h row
#define PRB     228                // partial per-batch stride (16B-aligned, bank-clean)
#define LVLSZ   (NB * PRB)         // 1824 floats per partial level
#define L1LV    2                  // L1 partial levels
#define L2LV    5                  // L2 partial levels

// ---- shared memory layout (float offsets) ----
#define OFF_W1   0                          // [13][224][4]
#define OFF_W2   (OFF_W1 + 13*GP*4)         // [26][224][4]
#define OFF_XS   (OFF_W2 + 26*GP*4)         // [512][8]
#define OFF_HS   (OFF_XS + TSTEPS*8)        // [8][108]
#define OFF_C1   (OFF_HS + NB*HROW)         // [8][52]
#define OFF_C2   (OFF_C1 + NB*52)           // [8][52]
#define OFF_PB1  (OFF_C2 + NB*52)           // 2 levels x [8][228]
#define OFF_PB2  (OFF_PB1 + L1LV*LVLSZ)     // 5 levels x [8][228]
#define OFF_B1   (OFF_PB2 + L2LV*LVLSZ)     // 224 (order 4u+q)
#define OFF_B2   (OFF_B1 + GP)              // 224
#define OFF_WI1  (OFF_B2 + GP)              // 224 (slot order)
#define OFF_WL   (OFF_WI1 + GP)             // 56
#define OFF_BL   (OFF_WL + 56)              // 4
#define SMEM_FLOATS (OFF_BL + 4)
#define SMEM_BYTES  (SMEM_FLOATS * 4)       // ~217 KB

__device__ __forceinline__ void ffma2(u64 &d, u64 a, u64 b) {
    asm("fma.rn.f32x2 %0, %1, %2, %0;" : "+l"(d) : "l"(a), "l"(b));
}
__device__ __forceinline__ float2 unpk(u64 v) {
    float2 r;
    asm("mov.b64 {%0, %1}, %2;" : "=f"(r.x), "=f"(r.y) : "l"(v));
    return r;
}
__device__ __forceinline__ float sigf(float x) {
    return __fdividef(1.0f, 1.0f + __expf(-x));
}
__device__ __forceinline__ float tanhfast(float x) {
    return __fdividef(2.0f, 1.0f + __expf(-2.0f * x)) - 1.0f;
}

// gate GEMV: warp covers NJ j-groups x ALL 8 batches over CNT k-chunks.
// w: LDS.128 unique per lane (once per chunk per j — HALF of R12's traffic);
// h: broadcast. Batches in 2 halves of 4 to bound liveness.
template<int CNT, int NJ>
__device__ __forceinline__ void gemv(const ulonglong2* __restrict__ wp,
                                     const ulonglong2* __restrict__ hp,
                                     u64 (&acc)[NJ][8])
{
#pragma unroll
    for (int j = 0; j < NJ; j++)
#pragma unroll
        for (int b = 0; b < 8; b++) acc[j][b] = 0ull;
#pragma unroll
    for (int i = 0; i < CNT; i++) {
        ulonglong2 w[NJ];
#pragma unroll
        for (int j = 0; j < NJ; j++) w[j] = wp[i * GP + 32 * j];
#pragma unroll
        for (int half = 0; half < 2; half++) {
            ulonglong2 h[4];
#pragma unroll
            for (int b = 0; b < 4; b++) h[b] = hp[(half * 4 + b) * HC + i];
#pragma unroll
            for (int j = 0; j < NJ; j++)
#pragma unroll
                for (int b = 0; b < 4; b++) {
                    ffma2(acc[j][half * 4 + b], w[j].x, h[b].x);
                    ffma2(acc[j][half * 4 + b], w[j].y, h[b].y);
                }
        }
    }
}

template<int NJ, bool ADDX>
__device__ __forceinline__ void store_p(float* __restrict__ pb,
                                        const float* __restrict__ wiP,
                                        u64 (&acc)[NJ][8],
                                        const float* __restrict__ xrow)
{
    float wi[NJ];
    if (ADDX) {
#pragma unroll
        for (int j = 0; j < NJ; j++) wi[j] = wiP[32 * j];
    }
#pragma unroll
    for (int b = 0; b < 8; b++) {
        float xv = ADDX ? xrow[b] : 0.0f;
#pragma unroll
        for (int j = 0; j < NJ; j++) {
            float2 p = unpk(acc[j][b]);
            float gv = p.x + p.y;
            if (ADDX) gv = fmaf(xv, wi[j], gv);
            pb[b * PRB + 32 * j] = gv;
        }
    }
}

// pointwise update: job (b = job&7, u = job>>3), 408 jobs over 384 thr (2 rounds).
// (u,q)-packed gates -> one float4 per level; uniform level counts (L1 2, L2 5).
__device__ __forceinline__ void cell_update(float* sm, int tid,
                                            bool doU2, bool doU1)
{
#pragma unroll
    for (int r = 0; r < 2; r++) {
        int job = tid + r * NTHR;
        if (job < NB * H_) {
            int b = job & 7, u = job >> 3;
            if (doU2) {
                const float* pb = sm + OFF_PB2 + b * PRB + 4 * u;
                float4 g = *(const float4*)(sm + OFF_B2 + 4 * u);
#pragma unroll
                for (int l = 0; l < L2LV; l++) {
                    float4 p = *(const float4*)(pb + l * LVLSZ);
                    g.x += p.x; g.y += p.y; g.z += p.z; g.w += p.w;
                }
                float c  = sm[OFF_C2 + b * 52 + u];
                float cn = sigf(g.y) * c + sigf(g.x) * tanhfast(g.z);
                float hn = sigf(g.w) * tanhfast(cn);
                sm[OFF_C2 + b * 52 + u] = cn;
                sm[OFF_HS + b * HROW + 52 + u] = hn;
            }
            if (doU1) {
                const float* pb = sm + OFF_PB1 + b * PRB + 4 * u;
                float4 g = *(const float4*)(sm + OFF_B1 + 4 * u);
#pragma unroll
                for (int l = 0; l < L1LV; l++) {
                    float4 p = *(const float4*)(pb + l * LVLSZ);
                    g.x += p.x; g.y += p.y; g.z += p.z; g.w += p.w;
                }
                float c  = sm[OFF_C1 + b * 52 + u];
                float cn = sigf(g.y) * c + sigf(g.x) * tanhfast(g.z);
                float hn = sigf(g.w) * tanhfast(cn);
                sm[OFF_C1 + b * 52 + u] = cn;
                sm[OFF_HS + b * HROW + u] = hn;
            }
        }
    }
}

__device__ __forceinline__ void out_phase(const float* sm, int lane, int bid,
                                          int tcol, float* __restrict__ out)
{
    int ob = lane & 7, part = lane >> 3;            // 4 parts x 13 k
    float a = 0.0f;
#pragma unroll
    for (int kk = 0; kk < 13; kk++) {
        int k = part * 13 + kk;                     // k=51 -> zero pad
        a = fmaf(sm[OFF_HS + ob * HROW + 52 + k], sm[OFF_WL + k], a);
    }
    a += __shfl_xor_sync(0xffffffffu, a, 8);
    a += __shfl_xor_sync(0xffffffffu, a, 16);
    if (lane < 8)
        out[(bid * NB + ob) * TSTEPS + tcol] = a + sm[OFF_BL];
}

__global__ void __launch_bounds__(NTHR, 1)
lstm_kernel(const float* __restrict__ input,
            const float* __restrict__ Wih1, const float* __restrict__ Whh1,
            const float* __restrict__ bih1, const float* __restrict__ bhh1,
            const float* __restrict__ Wih2, const float* __restrict__ Whh2,
            const float* __restrict__ bih2, const float* __restrict__ bhh2,
            const float* __restrict__ Wlin, const float* __restrict__ blin,
            float* __restrict__ out)
{
    extern __shared__ float sm[];
    const int tid  = threadIdx.x;
    const int bid  = blockIdx.x;
    const int lane = tid & 31;
    const int wid  = tid >> 5;            // 0..11

    // ---- staging (slot s = 4u+q; original gate row og = q*51+u) ----
    for (int i = tid; i < NB * HROW; i += NTHR) sm[OFF_HS + i] = 0.0f;
    for (int i = tid; i < NB * 52 * 2; i += NTHR) sm[OFF_C1 + i] = 0.0f;
    for (int i = tid; i < TSTEPS * 8; i += NTHR) {
        int t = i >> 3, bb = i & 7;
        sm[OFF_XS + i] = input[t * BTOT + bid * NB + bb];
    }
    for (int i = tid; i < 13 * GP * 4; i += NTHR) {
        int c = i & 3, s = (i >> 2) % GP, kq = i / (GP * 4);
        int u = s >> 2, q = s & 3, k = 4 * kq + c;
        float v = 0.0f;
        if (u < H_ && k < H_) v = Whh1[(q * H_ + u) * H_ + k];
        sm[OFF_W1 + i] = v;
    }
    for (int i = tid; i < 26 * GP * 4; i += NTHR) {
        int c = i & 3, s = (i >> 2) % GP, kq = i / (GP * 4);
        int u = s >> 2, q = s & 3, k = 4 * kq + c;
        float v = 0.0f;
        if (u < H_) {
            if (k < H_)                  v = Wih2[(q * H_ + u) * H_ + k];
            else if (k >= 52 && k < 103) v = Whh2[(q * H_ + u) * H_ + (k - 52)];
        }
        sm[OFF_W2 + i] = v;
    }
    for (int i = tid; i < GP; i += NTHR) {
        int u = i >> 2, q = i & 3;
        float b1 = 0.0f, b2 = 0.0f, w1 = 0.0f;
        if (u < H_) {
            int og = q * H_ + u;
            b1 = bih1[og] + bhh1[og];
            b2 = bih2[og] + bhh2[og];
            w1 = Wih1[og];
        }
        sm[OFF_B1  + i] = b1;
        sm[OFF_B2  + i] = b2;
        sm[OFF_WI1 + i] = w1;
    }
    if (tid < 56) sm[OFF_WL + tid] = (tid < H_) ? Wlin[tid] : 0.0f;
    if (tid == 0) sm[OFF_BL] = blin[0];
    __syncthreads();

    // ---- warp roles (units = chunks x NJ, mean 22.75) ----
    // w0 : L1 jA [0,6)  lvl0 +x (24)    w1 : L1 jA [6,13) lvl1 (28)
    // w2 : L1 jB [0,7)  lvl0 +x (21)    w3 : L1 jB [7,13) lvl1 + L2 jB [24,26) lvl4 (24)
    // w4 : L2 jA [0,6)  lvl0 (24)       w5 : L2 jA [6,12)  lvl1 (24)
    // w6 : L2 jA [12,18) lvl2 (24)      w7 : L2 jA [18,24) lvl3 (24)
    // w8 : L2 jA [24,26) lvl4 + L2 jB [0,4) lvl0 (20, +out duty)
    // w9 : L2 jB [4,11) lvl1 (21)       w10: L2 jB [11,18) lvl2 (21)
    // w11: L2 jB [18,24) lvl3 (18)
    // NOTE: jB offset = +128 slots = +128 ulonglong2 (one u64x2 per slot).
    const ulonglong2* W1p = (const ulonglong2*)(sm + OFF_W1);
    const ulonglong2* W2p = (const ulonglong2*)(sm + OFF_W2);
    const ulonglong2* Hp  = (const ulonglong2*)(sm + OFF_HS);
    const float* wiA = sm + OFF_WI1 + lane;           // jA x-weights base
    const float* wiB = sm + OFF_WI1 + lane + 128;     // jB (j>=4)

    // L1 segment pointers (warps 0-3)
    const int l1k0[4]  = {0, 6, 0, 7};
    const int l1lv[4]  = {0, 1, 0, 1};
    const bool l1jB    = (wid >= 2);
    const ulonglong2* wp1 = W1p + ((wid < 4) ? l1k0[wid] : 0) * GP + lane
                          + (l1jB ? 128 : 0);
    const ulonglong2* hp1 = Hp + ((wid < 4) ? l1k0[wid] : 0);
    float* pb1 = sm + OFF_PB1 + ((wid < 4) ? l1lv[wid] : 0) * LVLSZ + lane
               + (l1jB ? 128 : 0);

    // L2 segment pointers (warps 3-11; w8 has a second L2 segment)
    const int l2k0[12] = {0,0,0, 24, 0, 6, 12, 18, 24, 4, 11, 18};
    const int l2lv[12] = {0,0,0,  4, 0, 1,  2,  3,  4, 1,  2,  3};
    const bool l2jB    = (wid == 3 || wid >= 9);      // w3, w9-11 are jB (w8 seg1 is jA)
    const ulonglong2* wp2 = W2p + l2k0[wid] * GP + lane + (l2jB ? 128 : 0);
    const ulonglong2* hp2 = Hp + l2k0[wid];
    float* pb2 = sm + OFF_PB2 + l2lv[wid] * LVLSZ + lane + (l2jB ? 128 : 0);

    // w8 second segment: L2 jB [0,4) lvl0
    const ulonglong2* wp2b = W2p + lane + 128;
    const ulonglong2* hp2b = Hp;
    float* pb2b = sm + OFF_PB2 + lane + 128;

    auto do_l1 = [&](const float* xrow) {
        if (wid == 0)      { u64 a[4][8]; gemv<6,4>(wp1, hp1, a); store_p<4,true >(pb1, wiA, a, xrow); }
        else if (wid == 1) { u64 a[4][8]; gemv<7,4>(wp1, hp1, a); store_p<4,false>(pb1, wiA, a, xrow); }
        else if (wid == 2) { u64 a[3][8]; gemv<7,3>(wp1, hp1, a); store_p<3,true >(pb1, wiB, a, xrow); }
        else if (wid == 3) { u64 a[3][8]; gemv<6,3>(wp1, hp1, a); store_p<3,false>(pb1, wiB, a, xrow); }
    };
    auto do_l2 = [&]() {
        if (wid == 3)       { u64 a[3][8]; gemv<2,3>(wp2, hp2, a); store_p<3,false>(pb2, wiB, a, nullptr); }
        else if (wid == 8)  { u64 a[4][8]; gemv<2,4>(wp2, hp2, a); store_p<4,false>(pb2, wiA, a, nullptr);
                              u64 b[3][8]; gemv<4,3>(wp2b, hp2b, b); store_p<3,false>(pb2b, wiB, b, nullptr); }
        else if (wid >= 9)  { u64 a[3][8];
                              if (wid == 11) gemv<6,3>(wp2, hp2, a);
                              else           gemv<7,3>(wp2, hp2, a);
                              store_p<3,false>(pb2, wiB, a, nullptr); }
        else if (wid >= 4)  { u64 a[4][8]; gemv<6,4>(wp2, hp2, a); store_p<4,false>(pb2, wiA, a, nullptr); }
    };

    // ---- prologue: G1(0), U1(0) ----
    if (wid < 4) do_l1(sm + OFF_XS);
    __syncthreads();
    cell_update(sm, tid, false, true);
    __syncthreads();

    // ---- pipelined recurrence ----
    for (int t = 0; t < TSTEPS; t++) {
        // phase A: G2(t) + G1(t+1) + out(t-1)
        do_l2();
        if (wid < 4 && t + 1 < TSTEPS) do_l1(sm + OFF_XS + (t + 1) * 8);
        if (wid == 8 && t > 0) out_phase(sm, lane, bid, t - 1, out);
        __syncthreads();

        // phase B: U2(t) + U1(t+1)
        cell_update(sm, tid, true, t + 1 < TSTEPS);
        __syncthreads();
    }

    // ---- epilogue ----
    if (wid == 8) out_phase(sm, lane, bid, TSTEPS - 1, out);
}

extern "C" void kernel_launch(void* const* d_in, const int* in_sizes, int n_in,
                              void* d_out, int out_size)
{
    const float* input = (const float*)d_in[0];
    const float* Wih1  = (const float*)d_in[1];
    const float* Whh1  = (const float*)d_in[2];
    const float* bih1  = (const float*)d_in[3];
    const float* bhh1  = (const float*)d_in[4];
    const float* Wih2  = (const float*)d_in[5];
    const float* Whh2  = (const float*)d_in[6];
    const float* bih2  = (const float*)d_in[7];
    const float* bhh2  = (const float*)d_in[8];
    const float* Wlin  = (const float*)d_in[9];
    const float* blin  = (const float*)d_in[10];
    float* out = (float*)d_out;

    static bool attr_set = false;
    if (!attr_set) {
        cudaFuncSetAttribute(lstm_kernel,
                             cudaFuncAttributeMaxDynamicSharedMemorySize,
                             SMEM_BYTES);
        attr_set = true;
    }
    lstm_kernel<<<NBLK, NTHR, SMEM_BYTES>>>(input, Wih1, Whh1, bih1, bhh1,
                                            Wih2, Whh2, bih2, bhh2,
                                            Wlin, blin, out);
}

// round 16
// speedup vs baseline: 2.3394x; 1.3248x over previous
#include <cuda_runtime.h>

typedef unsigned long long u64;

#define H_      51
#define TSTEPS  512
#define BTOT    1024
#define NB      8
#define NBLK    (BTOT / NB)       // 128 blocks
#define NTHR    640               // 20 warps = 5/SMSP
#define GP      224               // padded gate slots (gate-major: i|f|g|o x51 +pad)
#define HROW    108               // h row: [h1(51)|pad|h2(51)|pad..]
#define HC      (HROW/4)          // 27 ulonglong2 per h row
#define PRB     228               // partial per-batch stride (228%32=4 -> conflict-free)
#define LVLSZ   (NB * PRB)        // 1824
#define L1LV    2
#define L2LV    4

// ---- shared memory layout (float offsets) ----
#define OFF_W1   0                          // [13][224][4]
#define OFF_W2   (OFF_W1 + 13*GP*4)         // [26][224][4]
#define OFF_XS   (OFF_W2 + 26*GP*4)         // [512][8]
#define OFF_HS   (OFF_XS + TSTEPS*8)        // [8][108]
#define OFF_C1   (OFF_HS + NB*HROW)         // [8][52]
#define OFF_C2   (OFF_C1 + NB*52)           // [8][52]
#define OFF_PB1  (OFF_C2 + NB*52)           // 2 levels x [8][228]
#define OFF_PB2  (OFF_PB1 + L1LV*LVLSZ)     // 4 levels x [8][228]
#define OFF_B1   (OFF_PB2 + L2LV*LVLSZ)     // 224
#define OFF_B2   (OFF_B1 + GP)              // 224
#define OFF_WI1  (OFF_B2 + GP)              // 224
#define OFF_WL   (OFF_WI1 + GP)             // 56
#define OFF_BL   (OFF_WL + 56)              // 4
#define SMEM_FLOATS (OFF_BL + 4)            // 52412
#define SMEM_BYTES  (SMEM_FLOATS * 4)       // ~205 KB

__device__ __forceinline__ void ffma2(u64 &d, u64 a, u64 b) {
    asm("fma.rn.f32x2 %0, %1, %2, %0;" : "+l"(d) : "l"(a), "l"(b));
}
__device__ __forceinline__ float2 unpk(u64 v) {
    float2 r;
    asm("mov.b64 {%0, %1}, %2;" : "=f"(r.x), "=f"(r.y) : "l"(v));
    return r;
}
__device__ __forceinline__ float sigf(float x) {
    return __fdividef(1.0f, 1.0f + __expf(-x));
}
__device__ __forceinline__ float tanhfast(float x) {
    return __fdividef(2.0f, 1.0f + __expf(-2.0f * x)) - 1.0f;
}

// gate GEMV (R6/R12-proven shape, NJ-parameterized): lane = slot col,
// warp covers batches bh*4..bh*4+3 over NKQ k-chunks x NJ j-groups.
template<int NKQ, int NJ>
__device__ __forceinline__ void gate_gemv(const ulonglong2* __restrict__ wp,
                                          const ulonglong2* __restrict__ hp,
                                          u64 (&acc)[NJ][4])
{
#pragma unroll
    for (int j = 0; j < NJ; j++)
#pragma unroll
        for (int b = 0; b < 4; b++) acc[j][b] = 0ull;
#pragma unroll
    for (int i = 0; i < NKQ; i++) {
        ulonglong2 h[4];
#pragma unroll
        for (int b = 0; b < 4; b++) h[b] = hp[b * HC + i];
#pragma unroll
        for (int j = 0; j < NJ; j++) {
            ulonglong2 w = wp[i * GP + 32 * j];
#pragma unroll
            for (int b = 0; b < 4; b++) {
                ffma2(acc[j][b], w.x, h[b].x);
                ffma2(acc[j][b], w.y, h[b].y);
            }
        }
    }
}

template<int NJ, bool ADDX>
__device__ __forceinline__ void store_partial(float* __restrict__ pb,
                                              const float* __restrict__ wiP,
                                              int bh, u64 (&acc)[NJ][4],
                                              const float* __restrict__ xrow)
{
    float wi[NJ];
    if (ADDX) {
#pragma unroll
        for (int j = 0; j < NJ; j++) wi[j] = wiP[32 * j];
    }
#pragma unroll
    for (int b = 0; b < 4; b++) {
        float xv = ADDX ? xrow[bh * 4 + b] : 0.0f;
#pragma unroll
        for (int j = 0; j < NJ; j++) {
            float2 p = unpk(acc[j][b]);
            float gv = p.x + p.y;
            if (ADDX) gv = fmaf(xv, wi[j], gv);
            pb[(bh * 4 + b) * PRB + 32 * j] = gv;
        }
    }
}

// merged pointwise update: U2(t) and U1(t+1), independent chains (ILP).
// 408 jobs, tid<408 (single round at 640 thr). Scalar conflict-free reads
// (addr = b*228 + u + {0,51,102,153}: banks 4b+u+off, all distinct per warp).
__device__ __forceinline__ void cell_update(float* sm, int tid,
                                            bool doU2, bool doU1)
{
    if (tid < NB * H_) {
        int b = tid & 7, u = tid >> 3;
        float gi2, gf2, gg2, go2, c2;
        float gi1, gf1, gg1, go1, c1;
        if (doU2) {
            const float* p2 = sm + OFF_PB2 + b * PRB + u;
            gi2 = sm[OFF_B2 + u];
            gf2 = sm[OFF_B2 + 51 + u];
            gg2 = sm[OFF_B2 + 102 + u];
            go2 = sm[OFF_B2 + 153 + u];
#pragma unroll
            for (int l = 0; l < L2LV; l++) {
                const float* p = p2 + l * LVLSZ;
                gi2 += p[0];
                gf2 += p[51];
                gg2 += p[102];
                go2 += p[153];
            }
            c2 = sm[OFF_C2 + b * 52 + u];
        }
        if (doU1) {
            const float* p1 = sm + OFF_PB1 + b * PRB + u;
            gi1 = sm[OFF_B1 + u];
            gf1 = sm[OFF_B1 + 51 + u];
            gg1 = sm[OFF_B1 + 102 + u];
            go1 = sm[OFF_B1 + 153 + u];
#pragma unroll
            for (int l = 0; l < L1LV; l++) {
                const float* p = p1 + l * LVLSZ;
                gi1 += p[0];
                gf1 += p[51];
                gg1 += p[102];
                go1 += p[153];
            }
            c1 = sm[OFF_C1 + b * 52 + u];
        }
        if (doU2) {
            float cn2 = sigf(gf2) * c2 + sigf(gi2) * tanhfast(gg2);
            float hn2 = sigf(go2) * tanhfast(cn2);
            sm[OFF_C2 + b * 52 + u] = cn2;
            sm[OFF_HS + b * HROW + 52 + u] = hn2;
        }
        if (doU1) {
            float cn1 = sigf(gf1) * c1 + sigf(gi1) * tanhfast(gg1);
            float hn1 = sigf(go1) * tanhfast(cn1);
            sm[OFF_C1 + b * 52 + u] = cn1;
            sm[OFF_HS + b * HROW + u] = hn1;
        }
    }
}

__device__ __forceinline__ void out_phase(const float* sm, int lane, int bid,
                                          int tcol, float* __restrict__ out)
{
    int ob = lane & 7, part = lane >> 3;            // 4 parts x 13 k
    float a = 0.0f;
#pragma unroll
    for (int kk = 0; kk < 13; kk++) {
        int k = part * 13 + kk;                     // k=51 -> zero pad
        a = fmaf(sm[OFF_HS + ob * HROW + 52 + k], sm[OFF_WL + k], a);
    }
    a += __shfl_xor_sync(0xffffffffu, a, 8);
    a += __shfl_xor_sync(0xffffffffu, a, 16);
    if (lane < 8)
        out[(bid * NB + ob) * TSTEPS + tcol] = a + sm[OFF_BL];
}

__global__ void __launch_bounds__(NTHR, 1)
lstm_kernel(const float* __restrict__ input,
            const float* __restrict__ Wih1, const float* __restrict__ Whh1,
            const float* __restrict__ bih1, const float* __restrict__ bhh1,
            const float* __restrict__ Wih2, const float* __restrict__ Whh2,
            const float* __restrict__ bih2, const float* __restrict__ bhh2,
            const float* __restrict__ Wlin, const float* __restrict__ blin,
            float* __restrict__ out)
{
    extern __shared__ float sm[];
    const int tid  = threadIdx.x;
    const int bid  = blockIdx.x;
    const int lane = tid & 31;
    const int wid  = tid >> 5;            // 0..19
    const int role = wid >> 1;            // 0..9
    const int bh   = wid & 1;             // batch half

    // ---- staging ----
    for (int i = tid; i < NB * HROW; i += NTHR) sm[OFF_HS + i] = 0.0f;
    for (int i = tid; i < NB * 52 * 2; i += NTHR) sm[OFF_C1 + i] = 0.0f;
    // zero partial buffers once: unwritten (level,col) regions stay 0 forever
    for (int i = tid; i < (L1LV + L2LV) * LVLSZ; i += NTHR) sm[OFF_PB1 + i] = 0.0f;
    for (int i = tid; i < TSTEPS * NB; i += NTHR) {
        int t = i >> 3, bb = i & 7;
        sm[OFF_XS + i] = input[t * BTOT + bid * NB + bb];
    }
    for (int i = tid; i < 13 * GP * 4; i += NTHR) {
        int c = i & 3, g = (i >> 2) % GP, kq = i / (GP * 4);
        int k = 4 * kq + c;
        sm[OFF_W1 + i] = (g < 204 && k < H_) ? Whh1[g * H_ + k] : 0.0f;
    }
    for (int i = tid; i < 26 * GP * 4; i += NTHR) {
        int c = i & 3, g = (i >> 2) % GP, kq = i / (GP * 4);
        int k = 4 * kq + c;
        float v = 0.0f;
        if (g < 204) {
            if (k < H_)                  v = Wih2[g * H_ + k];
            else if (k >= 52 && k < 103) v = Whh2[g * H_ + (k - 52)];
        }
        sm[OFF_W2 + i] = v;
    }
    for (int i = tid; i < GP; i += NTHR) {
        sm[OFF_B1  + i] = (i < 204) ? bih1[i] + bhh1[i] : 0.0f;
        sm[OFF_B2  + i] = (i < 204) ? bih2[i] + bhh2[i] : 0.0f;
        sm[OFF_WI1 + i] = (i < 204) ? Wih1[i] : 0.0f;
    }
    if (tid < 56) sm[OFF_WL + tid] = (tid < H_) ? Wlin[tid] : 0.0f;
    if (tid == 0) sm[OFF_BL] = blin[0];
    __syncthreads();

    // ---- roles (x2 bh = 20 warps). jA = j0..3 (cols 0-127), jB = j4..6.
    // r0: L1 jA [0,7)  lvl0 +x       r1: L1 jA [7,13)  lvl1
    // r2: L1 jB [0,10) lvl0 +x       r3: L1 jB [10,13) lvl1 + L2 jB [0,7) lvl0
    // r4: L2 jA [0,6)  lvl0 (+out)   r5: L2 jA [6,13)  lvl1
    // r6: L2 jA [13,20) lvl2         r7: L2 jA [20,26) lvl3
    // r8: L2 jB [7,17) lvl1          r9: L2 jB [17,26) lvl2
    // L2 lvl3 jB region: never written -> stays zero (read as 0 by update).
    const ulonglong2* W1p = (const ulonglong2*)(sm + OFF_W1);
    const ulonglong2* W2p = (const ulonglong2*)(sm + OFF_W2);
    const ulonglong2* Hp  = (const ulonglong2*)(sm + OFF_HS) + bh * 4 * HC;

    const int l1k0_t[4] = {0, 7, 0, 10};
    const int l1lv_t[4] = {0, 1, 0, 1};
    const int l1jb_t[4] = {0, 0, 1, 1};
    const int l2k0_t[10] = {0,0,0, 0, 0, 6, 13, 20, 7, 17};
    const int l2lv_t[10] = {0,0,0, 0, 0, 1,  2,  3, 1,  2};
    const int l2jb_t[10] = {0,0,0, 1, 0, 0,  0,  0, 1,  1};

    const bool hasL1 = (role <= 3);
    const bool hasL2 = (role >= 3);

    const int l1k0 = hasL1 ? l1k0_t[role] : 0;
    const int l1jo = hasL1 ? l1jb_t[role] * 128 : 0;
    const ulonglong2* wp1 = W1p + l1k0 * GP + lane + l1jo;
    const ulonglong2* hp1 = Hp + l1k0;
    float* pb1 = sm + OFF_PB1 + (hasL1 ? l1lv_t[role] : 0) * LVLSZ + lane + l1jo;
    const float* wi1 = sm + OFF_WI1 + lane + l1jo;

    const int l2k0 = l2k0_t[role];
    const int l2jo = l2jb_t[role] * 128;
    const ulonglong2* wp2 = W2p + l2k0 * GP + lane + l2jo;
    const ulonglong2* hp2 = Hp + l2k0;
    float* pb2 = sm + OFF_PB2 + l2lv_t[role] * LVLSZ + lane + l2jo;

    auto do_l1 = [&](const float* xrow) {
        if (role == 0)      { u64 a[4][4]; gate_gemv< 7,4>(wp1, hp1, a); store_partial<4,true >(pb1, wi1, bh, a, xrow); }
        else if (role == 1) { u64 a[4][4]; gate_gemv< 6,4>(wp1, hp1, a); store_partial<4,false>(pb1, wi1, bh, a, xrow); }
        else if (role == 2) { u64 a[3][4]; gate_gemv<10,3>(wp1, hp1, a); store_partial<3,true >(pb1, wi1, bh, a, xrow); }
        else if (role == 3) { u64 a[3][4]; gate_gemv< 3,3>(wp1, hp1, a); store_partial<3,false>(pb1, wi1, bh, a, xrow); }
    };
    auto do_l2 = [&]() {
        if (role == 3)      { u64 a[3][4]; gate_gemv< 7,3>(wp2, hp2, a); store_partial<3,false>(pb2, nullptr, bh, a, nullptr); }
        else if (role == 4) { u64 a[4][4]; gate_gemv< 6,4>(wp2, hp2, a); store_partial<4,false>(pb2, nullptr, bh, a, nullptr); }
        else if (role == 5) { u64 a[4][4]; gate_gemv< 7,4>(wp2, hp2, a); store_partial<4,false>(pb2, nullptr, bh, a, nullptr); }
        else if (role == 6) { u64 a[4][4]; gate_gemv< 7,4>(wp2, hp2, a); store_partial<4,false>(pb2, nullptr, bh, a, nullptr); }
        else if (role == 7) { u64 a[4][4]; gate_gemv< 6,4>(wp2, hp2, a); store_partial<4,false>(pb2, nullptr, bh, a, nullptr); }
        else if (role == 8) { u64 a[3][4]; gate_gemv<10,3>(wp2, hp2, a); store_partial<3,false>(pb2, nullptr, bh, a, nullptr); }
        else if (role == 9) { u64 a[3][4]; gate_gemv< 9,3>(wp2, hp2, a); store_partial<3,false>(pb2, nullptr, bh, a, nullptr); }
    };

    // ---- prologue: G1(0), U1(0) ----
    if (hasL1) do_l1(sm + OFF_XS);
    __syncthreads();
    cell_update(sm, tid, false, true);
    __syncthreads();

    // ---- pipelined recurrence ----
    for (int t = 0; t < TSTEPS; t++) {
        // phase A: G2(t) + G1(t+1) + out(t-1)
        if (hasL2) do_l2();
        if (hasL1 && t + 1 < TSTEPS) do_l1(sm + OFF_XS + (t + 1) * 8);
        if (wid == 8 && t > 0) out_phase(sm, lane, bid, t - 1, out);
        __syncthreads();

        // phase B: U2(t) + U1(t+1), merged (independent chains)
        cell_update(sm, tid, true, t + 1 < TSTEPS);
        __syncthreads();
    }

    // ---- epilogue ----
    if (wid == 8) out_phase(sm, lane, bid, TSTEPS - 1, out);
}

extern "C" void kernel_launch(void* const* d_in, const int* in_sizes, int n_in,
                              void* d_out, int out_size)
{
    const float* input = (const float*)d_in[0];
    const float* Wih1  = (const float*)d_in[1];
    const float* Whh1  = (const float*)d_in[2];
    const float* bih1  = (const float*)d_in[3];
    const float* bhh1  = (const float*)d_in[4];
    const float* Wih2  = (const float*)d_in[5];
    const float* Whh2  = (const float*)d_in[6];
    const float* bih2  = (const float*)d_in[7];
    const float* bhh2  = (const float*)d_in[8];
    const float* Wlin  = (const float*)d_in[9];
    const float* blin  = (const float*)d_in[10];
    float* out = (float*)d_out;

    static bool attr_set = false;
    if (!attr_set) {
        cudaFuncSetAttribute(lstm_kernel,
                             cudaFuncAttributeMaxDynamicSharedMemorySize,
                             SMEM_BYTES);
        attr_set = true;
    }
    lstm_kernel<<<NBLK, NTHR, SMEM_BYTES>>>(input, Wih1, Whh1, bih1, bhh1,
                                            Wih2, Whh2, bih2, bhh2,
                                            Wlin, blin, out);
}